// round 2
// baseline (speedup 1.0000x reference)
#include <cuda_runtime.h>
#include <cuda_bf16.h>
#include <cstdint>

#define NN 50000
#define BB 32
#define FF 200
#define EE 800000
#define E2 850000   // EE + NN self loops
#define NB (NN*BB)  // 1,600,000

// Scratch (L2-resident working set ~32MB)
__device__ float g_x[NB];     // fc1 output, node-major [n][b]
__device__ float g_s[NB];     // softmax denominator  sum(ex)
__device__ float g_t[NB];     // GAT numerator        sum(ex * x_src)
__device__ float g_xenc[NB];  // elu(gat out)
__device__ float g_u[NB];     // GCN numerator        sum(ex * xenc_src)
__device__ float g_logits[BB*4];

// ---------------------------------------------------------------- zero scratch
__global__ void k_zero() {
    int i = blockIdx.x * blockDim.x + threadIdx.x;
    if (i < NB) { g_s[i] = 0.f; g_t[i] = 0.f; g_u[i] = 0.f; }
    if (i < BB*4) g_logits[i] = 0.f;
}

// ---------------------------------------------------------------- fc1: x = fd @ W^T + b   -> node-major [n][32]
// block = 256 threads = 8 warps; each warp: 4 nodes (lane>>3), lane&7 selects batch-quad.
__global__ void k_fc1(const float* __restrict__ fd, const float* __restrict__ w,
                      const float* __restrict__ bias) {
    __shared__ __align__(16) float fdT[FF * BB];  // [k][b], 25.6KB
    int tid = threadIdx.x;
    for (int i = tid; i < FF * BB; i += blockDim.x) {
        int b = i / FF, k = i % FF;
        fdT[k * BB + b] = fd[i];
    }
    __syncthreads();

    int lane = tid & 31, warp = tid >> 5;
    int bq = lane & 7;        // batch quad: batches 4*bq..4*bq+3
    int nl = lane >> 3;       // node-in-warp 0..3
    int node = blockIdx.x * 32 + warp * 4 + nl;
    if (node >= NN) return;

    const float4* wrow = reinterpret_cast<const float4*>(w + (size_t)node * FF);
    const float4* fdv  = reinterpret_cast<const float4*>(fdT);
    float4 acc = make_float4(0.f, 0.f, 0.f, 0.f);

#pragma unroll 10
    for (int k4 = 0; k4 < FF / 4; ++k4) {
        float4 w4 = wrow[k4];
        float4 f0 = fdv[(k4 * 4 + 0) * 8 + bq];
        float4 f1 = fdv[(k4 * 4 + 1) * 8 + bq];
        float4 f2 = fdv[(k4 * 4 + 2) * 8 + bq];
        float4 f3 = fdv[(k4 * 4 + 3) * 8 + bq];
        acc.x += w4.x*f0.x + w4.y*f1.x + w4.z*f2.x + w4.w*f3.x;
        acc.y += w4.x*f0.y + w4.y*f1.y + w4.z*f2.y + w4.w*f3.y;
        acc.z += w4.x*f0.z + w4.y*f1.z + w4.z*f2.z + w4.w*f3.z;
        acc.w += w4.x*f0.w + w4.y*f1.w + w4.z*f2.w + w4.w*f3.w;
    }
    float bb = bias[node];
    acc.x += bb; acc.y += bb; acc.z += bb; acc.w += bb;
    reinterpret_cast<float4*>(g_x)[node * 8 + bq] = acc;
}

// ---------------------------------------------------------------- edge pass 1: s += ex, t += ex*x_src
// warp per edge, lane = batch
__global__ void k_edge1(const int* __restrict__ ei,
                        const float* __restrict__ gatw,
                        const float* __restrict__ asrc,
                        const float* __restrict__ adst) {
    int e = (blockIdx.x * blockDim.x + threadIdx.x) >> 5;
    int lane = threadIdx.x & 31;
    if (e >= E2) return;
    int src, dst;
    if (e < EE) { src = __ldg(ei + e); dst = __ldg(ei + EE + e); }
    else        { src = dst = e - EE; }
    float gw = __ldg(gatw);
    float p  = gw * __ldg(asrc);
    float q  = gw * __ldg(adst);
    float xs = g_x[src * 32 + lane];
    float xd = (src == dst) ? xs : g_x[dst * 32 + lane];
    float ev = p * xs + q * xd;
    ev = ev > 0.f ? ev : 0.2f * ev;          // leaky_relu 0.2
    float ex = __expf(ev);
    atomicAdd(&g_s[dst * 32 + lane], ex);
    atomicAdd(&g_t[dst * 32 + lane], ex * xs);
}

// ---------------------------------------------------------------- x_enc = elu(gw * t/s + gat_b)
__global__ void k_xenc(const float* __restrict__ gatw, const float* __restrict__ gatb) {
    int i = blockIdx.x * blockDim.x + threadIdx.x;
    if (i >= NB) return;
    float v = __ldg(gatw) * g_t[i] / g_s[i] + __ldg(gatb);
    g_xenc[i] = v > 0.f ? v : (__expf(v) - 1.f);
}

// ---------------------------------------------------------------- edge pass 2: u += ex * xenc_src
__global__ void k_edge2(const int* __restrict__ ei,
                        const float* __restrict__ gatw,
                        const float* __restrict__ asrc,
                        const float* __restrict__ adst) {
    int e = (blockIdx.x * blockDim.x + threadIdx.x) >> 5;
    int lane = threadIdx.x & 31;
    if (e >= E2) return;
    int src, dst;
    if (e < EE) { src = __ldg(ei + e); dst = __ldg(ei + EE + e); }
    else        { src = dst = e - EE; }
    float gw = __ldg(gatw);
    float p  = gw * __ldg(asrc);
    float q  = gw * __ldg(adst);
    float xs = g_x[src * 32 + lane];
    float xd = (src == dst) ? xs : g_x[dst * 32 + lane];
    float ev = p * xs + q * xd;
    ev = ev > 0.f ? ev : 0.2f * ev;
    float ex = __expf(ev);
    atomicAdd(&g_u[dst * 32 + lane], ex * g_xenc[src * 32 + lane]);
}

// ---------------------------------------------------------------- community epilogue: leaky->LN(C=3)->softmax -> out
__global__ void k_comm(const float* __restrict__ gcnw, const float* __restrict__ gcnb,
                       const float* __restrict__ lng, const float* __restrict__ lnb,
                       float* __restrict__ out) {
    int idx = blockIdx.x * blockDim.x + threadIdx.x;
    int n = idx >> 5, lane = idx & 31;    // lane = batch
    if (n >= NN) return;
    int i = n * 32 + lane;
    float y = g_u[i] / g_s[i];            // deg==1 -> norm == alpha

    float c0 = y * __ldg(gcnw + 0) + __ldg(gcnb + 0);
    float c1 = y * __ldg(gcnw + 1) + __ldg(gcnb + 1);
    float c2 = y * __ldg(gcnw + 2) + __ldg(gcnb + 2);
    c0 = c0 > 0.f ? c0 : 0.01f * c0;
    c1 = c1 > 0.f ? c1 : 0.01f * c1;
    c2 = c2 > 0.f ? c2 : 0.01f * c2;
    float mu = (c0 + c1 + c2) * (1.f / 3.f);
    float d0 = c0 - mu, d1 = c1 - mu, d2 = c2 - mu;
    float var = (d0 * d0 + d1 * d1 + d2 * d2) * (1.f / 3.f);
    float r = rsqrtf(var + 1e-5f);
    float v0 = d0 * r * __ldg(lng + 0) + __ldg(lnb + 0);
    float v1 = d1 * r * __ldg(lng + 1) + __ldg(lnb + 1);
    float v2 = d2 * r * __ldg(lng + 2) + __ldg(lnb + 2);
    float m = fmaxf(v0, fmaxf(v1, v2));
    float e0 = __expf(v0 - m), e1 = __expf(v1 - m), e2 = __expf(v2 - m);
    float inv = 1.f / (e0 + e1 + e2);

    size_t base = 128 + ((size_t)lane * NN + n) * 3;   // [b][n][c] after 128 logit floats
    out[base + 0] = e0 * inv;
    out[base + 1] = e1 * inv;
    out[base + 2] = e2 * inv;
}

// ---------------------------------------------------------------- classifier partial reduction
__global__ void k_logits(const float* __restrict__ clfw) {
    int wid = (blockIdx.x * blockDim.x + threadIdx.x) >> 5;
    int lane = threadIdx.x & 31;            // lane = batch
    int W = (gridDim.x * blockDim.x) >> 5;
    float a0 = 0.f, a1 = 0.f, a2 = 0.f, a3 = 0.f;
    for (int n = wid; n < NN; n += W) {
        float v = g_xenc[n * 32 + lane];
        a0 += v * __ldg(clfw + n);
        a1 += v * __ldg(clfw + NN + n);
        a2 += v * __ldg(clfw + 2 * NN + n);
        a3 += v * __ldg(clfw + 3 * NN + n);
    }
    atomicAdd(&g_logits[lane * 4 + 0], a0);
    atomicAdd(&g_logits[lane * 4 + 1], a1);
    atomicAdd(&g_logits[lane * 4 + 2], a2);
    atomicAdd(&g_logits[lane * 4 + 3], a3);
}

// ---------------------------------------------------------------- final: softmax over 4 logits per batch
__global__ void k_final(const float* __restrict__ clfb, float* __restrict__ out) {
    int b = threadIdx.x;
    if (b >= BB) return;
    float l0 = g_logits[b * 4 + 0] + __ldg(clfb + 0);
    float l1 = g_logits[b * 4 + 1] + __ldg(clfb + 1);
    float l2 = g_logits[b * 4 + 2] + __ldg(clfb + 2);
    float l3 = g_logits[b * 4 + 3] + __ldg(clfb + 3);
    float m = fmaxf(fmaxf(l0, l1), fmaxf(l2, l3));
    float e0 = __expf(l0 - m), e1 = __expf(l1 - m), e2 = __expf(l2 - m), e3 = __expf(l3 - m);
    float inv = 1.f / (e0 + e1 + e2 + e3);
    out[b * 4 + 0] = e0 * inv;
    out[b * 4 + 1] = e1 * inv;
    out[b * 4 + 2] = e2 * inv;
    out[b * 4 + 3] = e3 * inv;
}

extern "C" void kernel_launch(void* const* d_in, const int* in_sizes, int n_in,
                              void* d_out, int out_size) {
    const float* fd    = (const float*)d_in[0];   // [32,200]
    const float* fc1w  = (const float*)d_in[1];   // [50000,200]
    const float* fc1b  = (const float*)d_in[2];   // [50000]
    const float* gatw  = (const float*)d_in[3];   // [1,1]
    const float* asrc  = (const float*)d_in[4];   // [1]
    const float* adst  = (const float*)d_in[5];   // [1]
    const float* gatb  = (const float*)d_in[6];   // []
    const float* gcnw  = (const float*)d_in[7];   // [1,3]
    const float* gcnb  = (const float*)d_in[8];   // [3]
    const float* lng   = (const float*)d_in[9];   // [3]
    const float* lnb   = (const float*)d_in[10];  // [3]
    const float* clfw  = (const float*)d_in[11];  // [4,50000]
    const float* clfb  = (const float*)d_in[12];  // [4]
    const int*   ei    = (const int*)d_in[13];    // [2,800000]
    float* out = (float*)d_out;

    k_zero<<<(NB + 255) / 256, 256>>>();
    k_fc1<<<(NN + 31) / 32, 256>>>(fd, fc1w, fc1b);
    k_edge1<<<(E2 + 7) / 8, 256>>>(ei, gatw, asrc, adst);
    k_xenc<<<(NB + 255) / 256, 256>>>(gatw, gatb);
    k_edge2<<<(E2 + 7) / 8, 256>>>(ei, gatw, asrc, adst);
    k_comm<<<(NN * 32 + 255) / 256, 256>>>(gcnw, gcnb, lng, lnb, out);
    k_logits<<<64, 256>>>(clfw);
    k_final<<<1, 32>>>(clfb, out);
}

// round 5
// speedup vs baseline: 1.1996x; 1.1996x over previous
#include <cuda_runtime.h>
#include <cuda_bf16.h>
#include <cstdint>

#define NN 50000
#define BB 32
#define FF 200
#define EE 800000
#define NB (NN*BB)  // 1,600,000

// Scratch
__device__ float g_x[NB];      // fc1 output, node-major [n][b]
__device__ float g_s[NB];      // softmax denominator per (n,b)
__device__ float g_xenc[NB];   // elu(gat out)
__device__ float g_logits[BB*4];
__device__ int   g_cnt[NN];    // in-degree histogram (without self loops)
__device__ int   g_offs[NN+1]; // CSR offsets
__device__ int   g_cur[NN];    // scatter cursors
__device__ int   g_ssrc[EE];   // dst-sorted src indices

// ---------------------------------------------------------------- init: zero histogram + logits
__global__ void k_init() {
    int i = blockIdx.x * blockDim.x + threadIdx.x;
    if (i < NN) g_cnt[i] = 0;
    if (i < BB*4) g_logits[i] = 0.f;
}

// ---------------------------------------------------------------- degree histogram
__global__ void k_deg(const int* __restrict__ ei) {
    int e = blockIdx.x * blockDim.x + threadIdx.x;
    if (e >= EE) return;
    atomicAdd(&g_cnt[__ldg(ei + EE + e)], 1);
}

// ---------------------------------------------------------------- exclusive scan (single block, 1024 thr)
__global__ void k_scan() {
    const int T = 1024;
    const int CH = (NN + T - 1) / T;  // 49
    int t = threadIdx.x;
    int base = t * CH;
    int sum = 0;
    for (int i = 0; i < CH; ++i) {
        int idx = base + i;
        if (idx < NN) sum += g_cnt[idx];
    }
    __shared__ int sh[T];
    sh[t] = sum;
    __syncthreads();
    for (int off = 1; off < T; off <<= 1) {
        int v = (t >= off) ? sh[t - off] : 0;
        __syncthreads();
        sh[t] += v;
        __syncthreads();
    }
    int run = sh[t] - sum;  // exclusive prefix of this chunk
    for (int i = 0; i < CH; ++i) {
        int idx = base + i;
        if (idx < NN) {
            g_offs[idx] = run;
            g_cur[idx]  = run;
            run += g_cnt[idx];
        }
    }
    if (t == T - 1) g_offs[NN] = run;
}

// ---------------------------------------------------------------- scatter edges into dst buckets
__global__ void k_scatter(const int* __restrict__ ei) {
    int e = blockIdx.x * blockDim.x + threadIdx.x;
    if (e >= EE) return;
    int src = __ldg(ei + e);
    int dst = __ldg(ei + EE + e);
    int pos = atomicAdd(&g_cur[dst], 1);
    g_ssrc[pos] = src;
}

// ---------------------------------------------------------------- fc1: x = fd @ W^T + b -> node-major [n][32]
__global__ void k_fc1(const float* __restrict__ fd, const float* __restrict__ w,
                      const float* __restrict__ bias) {
    __shared__ __align__(16) float fdT[FF * BB];  // [k][b]
    int tid = threadIdx.x;
    for (int i = tid; i < FF * BB; i += blockDim.x) {
        int b = i / FF, k = i % FF;
        fdT[k * BB + b] = fd[i];
    }
    __syncthreads();

    int lane = tid & 31, warp = tid >> 5;
    int bq = lane & 7;        // batch quad
    int nl = lane >> 3;       // node-in-warp
    int node = blockIdx.x * 32 + warp * 4 + nl;
    if (node >= NN) return;

    const float4* wrow = reinterpret_cast<const float4*>(w + (size_t)node * FF);
    const float4* fdv  = reinterpret_cast<const float4*>(fdT);
    float4 acc = make_float4(0.f, 0.f, 0.f, 0.f);

#pragma unroll 10
    for (int k4 = 0; k4 < FF / 4; ++k4) {
        float4 w4 = wrow[k4];
        float4 f0 = fdv[(k4 * 4 + 0) * 8 + bq];
        float4 f1 = fdv[(k4 * 4 + 1) * 8 + bq];
        float4 f2 = fdv[(k4 * 4 + 2) * 8 + bq];
        float4 f3 = fdv[(k4 * 4 + 3) * 8 + bq];
        acc.x += w4.x*f0.x + w4.y*f1.x + w4.z*f2.x + w4.w*f3.x;
        acc.y += w4.x*f0.y + w4.y*f1.y + w4.z*f2.y + w4.w*f3.y;
        acc.z += w4.x*f0.z + w4.y*f1.z + w4.z*f2.z + w4.w*f3.z;
        acc.w += w4.x*f0.w + w4.y*f1.w + w4.z*f2.w + w4.w*f3.w;
    }
    float bb = bias[node];
    acc.x += bb; acc.y += bb; acc.z += bb; acc.w += bb;
    reinterpret_cast<float4*>(g_x)[node * 8 + bq] = acc;
}

// ---------------------------------------------------------------- GAT pass: warp per dst node, lane = batch
// s = sum(ex), t = sum(ex * x_src)  (incl. self loop), then xenc = elu(gw*t/s + b)
__global__ void k_gat(const float* __restrict__ gatw, const float* __restrict__ asrc,
                      const float* __restrict__ adst, const float* __restrict__ gatb) {
    int n = blockIdx.x * 8 + (threadIdx.x >> 5);
    int lane = threadIdx.x & 31;
    if (n >= NN) return;
    float gw = __ldg(gatw);
    float p  = gw * __ldg(asrc);
    float q  = gw * __ldg(adst);

    float xd = g_x[n * 32 + lane];
    // self loop
    float ev = (p + q) * xd;
    ev = ev > 0.f ? ev : 0.2f * ev;
    float ex = __expf(ev);
    float s = ex, t = ex * xd;

    int beg = g_offs[n], end = g_offs[n + 1];
    int j = beg;
    for (; j + 4 <= end; j += 4) {
        int s0 = g_ssrc[j], s1 = g_ssrc[j+1], s2 = g_ssrc[j+2], s3 = g_ssrc[j+3];
        float x0 = g_x[s0 * 32 + lane];
        float x1 = g_x[s1 * 32 + lane];
        float x2 = g_x[s2 * 32 + lane];
        float x3 = g_x[s3 * 32 + lane];
        float e0 = p*x0 + q*xd; e0 = e0 > 0.f ? e0 : 0.2f*e0; e0 = __expf(e0);
        float e1 = p*x1 + q*xd; e1 = e1 > 0.f ? e1 : 0.2f*e1; e1 = __expf(e1);
        float e2 = p*x2 + q*xd; e2 = e2 > 0.f ? e2 : 0.2f*e2; e2 = __expf(e2);
        float e3 = p*x3 + q*xd; e3 = e3 > 0.f ? e3 : 0.2f*e3; e3 = __expf(e3);
        s += (e0 + e1) + (e2 + e3);
        t += (e0*x0 + e1*x1) + (e2*x2 + e3*x3);
    }
    for (; j < end; ++j) {
        int sj = g_ssrc[j];
        float xs = g_x[sj * 32 + lane];
        float e = p*xs + q*xd; e = e > 0.f ? e : 0.2f*e; e = __expf(e);
        s += e; t += e * xs;
    }

    g_s[n * 32 + lane] = s;
    float v = gw * t / s + __ldg(gatb);
    g_xenc[n * 32 + lane] = v > 0.f ? v : (__expf(v) - 1.f);
}

// ---------------------------------------------------------------- GCN pass + community epilogue + coalesced out
// u = sum(ex * xenc_src); y = u/s; leaky -> LN(3) -> softmax -> out[b][n][c]
__global__ void k_gcn(const float* __restrict__ gatw, const float* __restrict__ asrc,
                      const float* __restrict__ adst,
                      const float* __restrict__ gcnw, const float* __restrict__ gcnb,
                      const float* __restrict__ lng, const float* __restrict__ lnb,
                      float* __restrict__ out) {
    __shared__ float sout[BB][25];  // [b][node_in_block*3 + c], padded
    int w = threadIdx.x >> 5;
    int n = blockIdx.x * 8 + w;
    int lane = threadIdx.x & 31;
    float gw = __ldg(gatw);
    float p  = gw * __ldg(asrc);
    float q  = gw * __ldg(adst);

    float xd = g_x[n * 32 + lane];
    float ev = (p + q) * xd;
    ev = ev > 0.f ? ev : 0.2f * ev;
    float ex = __expf(ev);
    float u = ex * g_xenc[n * 32 + lane];

    int beg = g_offs[n], end = g_offs[n + 1];
    int j = beg;
    for (; j + 4 <= end; j += 4) {
        int s0 = g_ssrc[j], s1 = g_ssrc[j+1], s2 = g_ssrc[j+2], s3 = g_ssrc[j+3];
        float x0 = g_x[s0 * 32 + lane];
        float x1 = g_x[s1 * 32 + lane];
        float x2 = g_x[s2 * 32 + lane];
        float x3 = g_x[s3 * 32 + lane];
        float h0 = g_xenc[s0 * 32 + lane];
        float h1 = g_xenc[s1 * 32 + lane];
        float h2 = g_xenc[s2 * 32 + lane];
        float h3 = g_xenc[s3 * 32 + lane];
        float e0 = p*x0 + q*xd; e0 = e0 > 0.f ? e0 : 0.2f*e0; e0 = __expf(e0);
        float e1 = p*x1 + q*xd; e1 = e1 > 0.f ? e1 : 0.2f*e1; e1 = __expf(e1);
        float e2 = p*x2 + q*xd; e2 = e2 > 0.f ? e2 : 0.2f*e2; e2 = __expf(e2);
        float e3 = p*x3 + q*xd; e3 = e3 > 0.f ? e3 : 0.2f*e3; e3 = __expf(e3);
        u += (e0*h0 + e1*h1) + (e2*h2 + e3*h3);
    }
    for (; j < end; ++j) {
        int sj = g_ssrc[j];
        float xs = g_x[sj * 32 + lane];
        float e = p*xs + q*xd; e = e > 0.f ? e : 0.2f*e; e = __expf(e);
        u += e * g_xenc[sj * 32 + lane];
    }

    float y = u / g_s[n * 32 + lane];   // deg==1 after softmax -> norm == alpha

    float c0 = y * __ldg(gcnw + 0) + __ldg(gcnb + 0);
    float c1 = y * __ldg(gcnw + 1) + __ldg(gcnb + 1);
    float c2 = y * __ldg(gcnw + 2) + __ldg(gcnb + 2);
    c0 = c0 > 0.f ? c0 : 0.01f * c0;
    c1 = c1 > 0.f ? c1 : 0.01f * c1;
    c2 = c2 > 0.f ? c2 : 0.01f * c2;
    float mu = (c0 + c1 + c2) * (1.f / 3.f);
    float d0 = c0 - mu, d1 = c1 - mu, d2 = c2 - mu;
    float var = (d0*d0 + d1*d1 + d2*d2) * (1.f / 3.f);
    float r = rsqrtf(var + 1e-5f);
    float v0 = d0 * r * __ldg(lng + 0) + __ldg(lnb + 0);
    float v1 = d1 * r * __ldg(lng + 1) + __ldg(lnb + 1);
    float v2 = d2 * r * __ldg(lng + 2) + __ldg(lnb + 2);
    float m = fmaxf(v0, fmaxf(v1, v2));
    float a0 = __expf(v0 - m), a1 = __expf(v1 - m), a2 = __expf(v2 - m);
    float inv = 1.f / (a0 + a1 + a2);

    sout[lane][w * 3 + 0] = a0 * inv;
    sout[lane][w * 3 + 1] = a1 * inv;
    sout[lane][w * 3 + 2] = a2 * inv;
    __syncthreads();

    // coalesced write: tid -> (b = tid/8, seg = tid%8); 8 nodes * 3 floats contiguous per b
    int b = threadIdx.x >> 3, seg = threadIdx.x & 7;
    int n0 = blockIdx.x * 8;
    size_t base = 128 + ((size_t)b * NN + n0 + seg) * 3;
    out[base + 0] = sout[b][seg * 3 + 0];
    out[base + 1] = sout[b][seg * 3 + 1];
    out[base + 2] = sout[b][seg * 3 + 2];
}

// ---------------------------------------------------------------- classifier partial reduction
__global__ void k_logits(const float* __restrict__ clfw) {
    int wid = (blockIdx.x * blockDim.x + threadIdx.x) >> 5;
    int lane = threadIdx.x & 31;            // lane = batch
    int W = (gridDim.x * blockDim.x) >> 5;
    float a0 = 0.f, a1 = 0.f, a2 = 0.f, a3 = 0.f;
    for (int n = wid; n < NN; n += W) {
        float v = g_xenc[n * 32 + lane];
        a0 += v * __ldg(clfw + n);
        a1 += v * __ldg(clfw + NN + n);
        a2 += v * __ldg(clfw + 2 * NN + n);
        a3 += v * __ldg(clfw + 3 * NN + n);
    }
    atomicAdd(&g_logits[lane * 4 + 0], a0);
    atomicAdd(&g_logits[lane * 4 + 1], a1);
    atomicAdd(&g_logits[lane * 4 + 2], a2);
    atomicAdd(&g_logits[lane * 4 + 3], a3);
}

// ---------------------------------------------------------------- final softmax over 4 logits per batch
__global__ void k_final(const float* __restrict__ clfb, float* __restrict__ out) {
    int b = threadIdx.x;
    if (b >= BB) return;
    float l0 = g_logits[b * 4 + 0] + __ldg(clfb + 0);
    float l1 = g_logits[b * 4 + 1] + __ldg(clfb + 1);
    float l2 = g_logits[b * 4 + 2] + __ldg(clfb + 2);
    float l3 = g_logits[b * 4 + 3] + __ldg(clfb + 3);
    float m = fmaxf(fmaxf(l0, l1), fmaxf(l2, l3));
    float e0 = __expf(l0 - m), e1 = __expf(l1 - m), e2 = __expf(l2 - m), e3 = __expf(l3 - m);
    float inv = 1.f / (e0 + e1 + e2 + e3);
    out[b * 4 + 0] = e0 * inv;
    out[b * 4 + 1] = e1 * inv;
    out[b * 4 + 2] = e2 * inv;
    out[b * 4 + 3] = e3 * inv;
}

extern "C" void kernel_launch(void* const* d_in, const int* in_sizes, int n_in,
                              void* d_out, int out_size) {
    const float* fd    = (const float*)d_in[0];
    const float* fc1w  = (const float*)d_in[1];
    const float* fc1b  = (const float*)d_in[2];
    const float* gatw  = (const float*)d_in[3];
    const float* asrc  = (const float*)d_in[4];
    const float* adst  = (const float*)d_in[5];
    const float* gatb  = (const float*)d_in[6];
    const float* gcnw  = (const float*)d_in[7];
    const float* gcnb  = (const float*)d_in[8];
    const float* lng   = (const float*)d_in[9];
    const float* lnb   = (const float*)d_in[10];
    const float* clfw  = (const float*)d_in[11];
    const float* clfb  = (const float*)d_in[12];
    const int*   ei    = (const int*)d_in[13];
    float* out = (float*)d_out;

    k_init<<<(NN + 255) / 256, 256>>>();
    k_deg<<<(EE + 255) / 256, 256>>>(ei);
    k_scan<<<1, 1024>>>();
    k_scatter<<<(EE + 255) / 256, 256>>>(ei);
    k_fc1<<<(NN + 31) / 32, 256>>>(fd, fc1w, fc1b);
    k_gat<<<NN / 8, 256>>>(gatw, asrc, adst, gatb);
    k_gcn<<<NN / 8, 256>>>(gatw, asrc, adst, gcnw, gcnb, lng, lnb, out);
    k_logits<<<64, 256>>>(clfw);
    k_final<<<1, 32>>>(clfb, out);
}

// round 9
// speedup vs baseline: 1.3440x; 1.1204x over previous
#include <cuda_runtime.h>
#include <cuda_bf16.h>
#include <cstdint>

#define NN 50000
#define BB 32
#define FF 200
#define EE 800000
#define NB (NN*BB)  // 1,600,000

// Scratch
__device__ float g_x[NB];      // fc1 output, node-major [n][b]
__device__ float g_s[NB];      // softmax denominator per (n,b)
__device__ float g_xenc[NB];   // elu(gat out)
__device__ float g_logits[BB*4];
__device__ int   g_cnt[NN];    // in-degree histogram (without self loops)
__device__ int   g_offs[NN+1]; // CSR offsets
__device__ int   g_rank[EE];   // rank of edge within its dst bucket
__device__ int   g_ssrc[EE];   // dst-sorted src indices

// ---------------------------------------------------------------- init: zero histogram + logits
__global__ void k_init() {
    int i = blockIdx.x * blockDim.x + threadIdx.x;
    if (i < NN) g_cnt[i] = 0;
    if (i < BB*4) g_logits[i] = 0.f;
}

// ---------------------------------------------------------------- degree histogram + per-edge rank
__global__ void k_deg(const int* __restrict__ ei) {
    int e = blockIdx.x * blockDim.x + threadIdx.x;
    if (e >= EE) return;
    int dst = __ldg(ei + EE + e);
    g_rank[e] = atomicAdd(&g_cnt[dst], 1);
}

// ---------------------------------------------------------------- exclusive scan (single block, 1024 thr)
__global__ void k_scan() {
    const int T = 1024;
    const int CH = (NN + T - 1) / T;  // 49
    int t = threadIdx.x;
    int base = t * CH;
    int sum = 0;
    for (int i = 0; i < CH; ++i) {
        int idx = base + i;
        if (idx < NN) sum += g_cnt[idx];
    }
    __shared__ int sh[T];
    sh[t] = sum;
    __syncthreads();
    for (int off = 1; off < T; off <<= 1) {
        int v = (t >= off) ? sh[t - off] : 0;
        __syncthreads();
        sh[t] += v;
        __syncthreads();
    }
    int run = sh[t] - sum;  // exclusive prefix of this chunk
    for (int i = 0; i < CH; ++i) {
        int idx = base + i;
        if (idx < NN) {
            g_offs[idx] = run;
            run += g_cnt[idx];
        }
    }
    if (t == T - 1) g_offs[NN] = run;
}

// ---------------------------------------------------------------- scatter (atomic-free: offs + precomputed rank)
__global__ void k_scatter(const int* __restrict__ ei) {
    int e = blockIdx.x * blockDim.x + threadIdx.x;
    if (e >= EE) return;
    int src = __ldg(ei + e);
    int dst = __ldg(ei + EE + e);
    g_ssrc[g_offs[dst] + g_rank[e]] = src;
}

// ---------------------------------------------------------------- fc1: register-tiled 4 nodes x 4 batches / thread
// lane = nq*8 + bq; thread's nodes = wbase + nq + 4*r (same-nq lanes broadcast w loads)
// fd is 25.6KB -> L1-resident; no shared memory at all.
__global__ void k_fc1(const float* __restrict__ fd, const float* __restrict__ w,
                      const float* __restrict__ bias) {
    int lane = threadIdx.x & 31, warp = threadIdx.x >> 5;
    int nq = lane >> 3;           // 0..3
    int bq = lane & 7;            // 0..7 -> batches 4*bq..4*bq+3
    int wbase = (blockIdx.x * 8 + warp) * 16;  // 16 nodes per warp
    int n0 = wbase + nq;          // nodes n0, n0+4, n0+8, n0+12

    const float4* f0 = reinterpret_cast<const float4*>(fd + (size_t)(bq * 4 + 0) * FF);
    const float4* f1 = reinterpret_cast<const float4*>(fd + (size_t)(bq * 4 + 1) * FF);
    const float4* f2 = reinterpret_cast<const float4*>(fd + (size_t)(bq * 4 + 2) * FF);
    const float4* f3 = reinterpret_cast<const float4*>(fd + (size_t)(bq * 4 + 3) * FF);

    bool v0 = (n0      < NN), v1 = (n0 + 4  < NN),
         v2 = (n0 + 8  < NN), v3 = (n0 + 12 < NN);
    // safe row pointers (clamp to row 0 when OOB; result discarded)
    const float4* w0 = reinterpret_cast<const float4*>(w + (v0 ? (size_t)n0        * FF : 0));
    const float4* w1 = reinterpret_cast<const float4*>(w + (v1 ? (size_t)(n0 + 4)  * FF : 0));
    const float4* w2 = reinterpret_cast<const float4*>(w + (v2 ? (size_t)(n0 + 8)  * FF : 0));
    const float4* w3 = reinterpret_cast<const float4*>(w + (v3 ? (size_t)(n0 + 12) * FF : 0));

    float4 a0 = make_float4(0.f,0.f,0.f,0.f);   // node r, over 4 batches
    float4 a1 = a0, a2 = a0, a3 = a0;

#pragma unroll 5
    for (int k4 = 0; k4 < FF / 4; ++k4) {
        float4 q0 = __ldg(f0 + k4), q1 = __ldg(f1 + k4),
               q2 = __ldg(f2 + k4), q3 = __ldg(f3 + k4);
        float4 r0 = __ldg(w0 + k4), r1 = __ldg(w1 + k4),
               r2 = __ldg(w2 + k4), r3 = __ldg(w3 + k4);
#define DOT4(wv, fv) (wv.x*fv.x + wv.y*fv.y + wv.z*fv.z + wv.w*fv.w)
        a0.x += DOT4(r0, q0); a0.y += DOT4(r0, q1); a0.z += DOT4(r0, q2); a0.w += DOT4(r0, q3);
        a1.x += DOT4(r1, q0); a1.y += DOT4(r1, q1); a1.z += DOT4(r1, q2); a1.w += DOT4(r1, q3);
        a2.x += DOT4(r2, q0); a2.y += DOT4(r2, q1); a2.z += DOT4(r2, q2); a2.w += DOT4(r2, q3);
        a3.x += DOT4(r3, q0); a3.y += DOT4(r3, q1); a3.z += DOT4(r3, q2); a3.w += DOT4(r3, q3);
#undef DOT4
    }
    float4* gx = reinterpret_cast<float4*>(g_x);
    if (v0) { float b = __ldg(bias + n0);
        a0.x += b; a0.y += b; a0.z += b; a0.w += b; gx[(size_t)n0 * 8 + bq] = a0; }
    if (v1) { float b = __ldg(bias + n0 + 4);
        a1.x += b; a1.y += b; a1.z += b; a1.w += b; gx[(size_t)(n0 + 4) * 8 + bq] = a1; }
    if (v2) { float b = __ldg(bias + n0 + 8);
        a2.x += b; a2.y += b; a2.z += b; a2.w += b; gx[(size_t)(n0 + 8) * 8 + bq] = a2; }
    if (v3) { float b = __ldg(bias + n0 + 12);
        a3.x += b; a3.y += b; a3.z += b; a3.w += b; gx[(size_t)(n0 + 12) * 8 + bq] = a3; }
}

// ---------------------------------------------------------------- GAT pass: warp per dst node, lane = batch
// deep-MLP: prefetch 8 indices, then 8 independent gathers
__global__ void k_gat(const float* __restrict__ gatw, const float* __restrict__ asrc,
                      const float* __restrict__ adst, const float* __restrict__ gatb) {
    int n = blockIdx.x * 8 + (threadIdx.x >> 5);
    int lane = threadIdx.x & 31;
    float gw = __ldg(gatw);
    float p  = gw * __ldg(asrc);
    float q  = gw * __ldg(adst);

    float xd = g_x[n * 32 + lane];
    float qxd = q * xd;
    float ev = p * xd + qxd;
    ev = ev > 0.f ? ev : 0.2f * ev;
    float ex = __expf(ev);
    float s = ex, t = ex * xd;

    int beg = g_offs[n], end = g_offs[n + 1];
    int j = beg;
    for (; j + 8 <= end; j += 8) {
        int idx[8];
#pragma unroll
        for (int r = 0; r < 8; ++r) idx[r] = __ldg(g_ssrc + j + r);
        float xv[8];
#pragma unroll
        for (int r = 0; r < 8; ++r) xv[r] = g_x[idx[r] * 32 + lane];
#pragma unroll
        for (int r = 0; r < 8; ++r) {
            float e = fmaf(p, xv[r], qxd);
            e = e > 0.f ? e : 0.2f * e;
            e = __expf(e);
            s += e; t = fmaf(e, xv[r], t);
        }
    }
    for (; j < end; ++j) {
        float xs = g_x[__ldg(g_ssrc + j) * 32 + lane];
        float e = fmaf(p, xs, qxd);
        e = e > 0.f ? e : 0.2f * e;
        e = __expf(e);
        s += e; t = fmaf(e, xs, t);
    }

    g_s[n * 32 + lane] = s;
    float v = gw * t / s + __ldg(gatb);
    g_xenc[n * 32 + lane] = v > 0.f ? v : (__expf(v) - 1.f);
}

// ---------------------------------------------------------------- GCN pass + community epilogue + coalesced out
__global__ void k_gcn(const float* __restrict__ gatw, const float* __restrict__ asrc,
                      const float* __restrict__ adst,
                      const float* __restrict__ gcnw, const float* __restrict__ gcnb,
                      const float* __restrict__ lng, const float* __restrict__ lnb,
                      float* __restrict__ out) {
    __shared__ float sout[BB][25];  // [b][node_in_block*3 + c], padded
    int w = threadIdx.x >> 5;
    int n = blockIdx.x * 8 + w;
    int lane = threadIdx.x & 31;
    float gw = __ldg(gatw);
    float p  = gw * __ldg(asrc);
    float q  = gw * __ldg(adst);

    float xd = g_x[n * 32 + lane];
    float qxd = q * xd;
    float ev = p * xd + qxd;
    ev = ev > 0.f ? ev : 0.2f * ev;
    float ex = __expf(ev);
    float u = ex * g_xenc[n * 32 + lane];

    int beg = g_offs[n], end = g_offs[n + 1];
    int j = beg;
    for (; j + 8 <= end; j += 8) {
        int idx[8];
#pragma unroll
        for (int r = 0; r < 8; ++r) idx[r] = __ldg(g_ssrc + j + r);
        float xv[8], hv[8];
#pragma unroll
        for (int r = 0; r < 8; ++r) xv[r] = g_x[idx[r] * 32 + lane];
#pragma unroll
        for (int r = 0; r < 8; ++r) hv[r] = g_xenc[idx[r] * 32 + lane];
#pragma unroll
        for (int r = 0; r < 8; ++r) {
            float e = fmaf(p, xv[r], qxd);
            e = e > 0.f ? e : 0.2f * e;
            e = __expf(e);
            u = fmaf(e, hv[r], u);
        }
    }
    for (; j < end; ++j) {
        int sj = __ldg(g_ssrc + j);
        float xs = g_x[sj * 32 + lane];
        float e = fmaf(p, xs, qxd);
        e = e > 0.f ? e : 0.2f * e;
        e = __expf(e);
        u = fmaf(e, g_xenc[sj * 32 + lane], u);
    }

    float y = u / g_s[n * 32 + lane];   // weighted degree == 1 -> norm == alpha

    float c0 = y * __ldg(gcnw + 0) + __ldg(gcnb + 0);
    float c1 = y * __ldg(gcnw + 1) + __ldg(gcnb + 1);
    float c2 = y * __ldg(gcnw + 2) + __ldg(gcnb + 2);
    c0 = c0 > 0.f ? c0 : 0.01f * c0;
    c1 = c1 > 0.f ? c1 : 0.01f * c1;
    c2 = c2 > 0.f ? c2 : 0.01f * c2;
    float mu = (c0 + c1 + c2) * (1.f / 3.f);
    float d0 = c0 - mu, d1 = c1 - mu, d2 = c2 - mu;
    float var = (d0*d0 + d1*d1 + d2*d2) * (1.f / 3.f);
    float r = rsqrtf(var + 1e-5f);
    float v0 = d0 * r * __ldg(lng + 0) + __ldg(lnb + 0);
    float v1 = d1 * r * __ldg(lng + 1) + __ldg(lnb + 1);
    float v2 = d2 * r * __ldg(lng + 2) + __ldg(lnb + 2);
    float m = fmaxf(v0, fmaxf(v1, v2));
    float a0 = __expf(v0 - m), a1 = __expf(v1 - m), a2 = __expf(v2 - m);
    float inv = 1.f / (a0 + a1 + a2);

    sout[lane][w * 3 + 0] = a0 * inv;
    sout[lane][w * 3 + 1] = a1 * inv;
    sout[lane][w * 3 + 2] = a2 * inv;
    __syncthreads();

    // coalesced write: tid -> (b = tid/8, seg = tid%8); 8 nodes * 3 floats contiguous per b
    int b = threadIdx.x >> 3, seg = threadIdx.x & 7;
    int n0 = blockIdx.x * 8;
    size_t base = 128 + ((size_t)b * NN + n0 + seg) * 3;
    out[base + 0] = sout[b][seg * 3 + 0];
    out[base + 1] = sout[b][seg * 3 + 1];
    out[base + 2] = sout[b][seg * 3 + 2];
}

// ---------------------------------------------------------------- classifier partial reduction
__global__ void k_logits(const float* __restrict__ clfw) {
    int wid = (blockIdx.x * blockDim.x + threadIdx.x) >> 5;
    int lane = threadIdx.x & 31;            // lane = batch
    int W = (gridDim.x * blockDim.x) >> 5;
    float a0 = 0.f, a1 = 0.f, a2 = 0.f, a3 = 0.f;
    for (int n = wid; n < NN; n += W) {
        float v = g_xenc[n * 32 + lane];
        a0 = fmaf(v, __ldg(clfw + n),          a0);
        a1 = fmaf(v, __ldg(clfw + NN + n),     a1);
        a2 = fmaf(v, __ldg(clfw + 2 * NN + n), a2);
        a3 = fmaf(v, __ldg(clfw + 3 * NN + n), a3);
    }
    atomicAdd(&g_logits[lane * 4 + 0], a0);
    atomicAdd(&g_logits[lane * 4 + 1], a1);
    atomicAdd(&g_logits[lane * 4 + 2], a2);
    atomicAdd(&g_logits[lane * 4 + 3], a3);
}

// ---------------------------------------------------------------- final softmax over 4 logits per batch
__global__ void k_final(const float* __restrict__ clfb, float* __restrict__ out) {
    int b = threadIdx.x;
    if (b >= BB) return;
    float l0 = g_logits[b * 4 + 0] + __ldg(clfb + 0);
    float l1 = g_logits[b * 4 + 1] + __ldg(clfb + 1);
    float l2 = g_logits[b * 4 + 2] + __ldg(clfb + 2);
    float l3 = g_logits[b * 4 + 3] + __ldg(clfb + 3);
    float m = fmaxf(fmaxf(l0, l1), fmaxf(l2, l3));
    float e0 = __expf(l0 - m), e1 = __expf(l1 - m), e2 = __expf(l2 - m), e3 = __expf(l3 - m);
    float inv = 1.f / (e0 + e1 + e2 + e3);
    out[b * 4 + 0] = e0 * inv;
    out[b * 4 + 1] = e1 * inv;
    out[b * 4 + 2] = e2 * inv;
    out[b * 4 + 3] = e3 * inv;
}

extern "C" void kernel_launch(void* const* d_in, const int* in_sizes, int n_in,
                              void* d_out, int out_size) {
    const float* fd    = (const float*)d_in[0];
    const float* fc1w  = (const float*)d_in[1];
    const float* fc1b  = (const float*)d_in[2];
    const float* gatw  = (const float*)d_in[3];
    const float* asrc  = (const float*)d_in[4];
    const float* adst  = (const float*)d_in[5];
    const float* gatb  = (const float*)d_in[6];
    const float* gcnw  = (const float*)d_in[7];
    const float* gcnb  = (const float*)d_in[8];
    const float* lng   = (const float*)d_in[9];
    const float* lnb   = (const float*)d_in[10];
    const float* clfw  = (const float*)d_in[11];
    const float* clfb  = (const float*)d_in[12];
    const int*   ei    = (const int*)d_in[13];
    float* out = (float*)d_out;

    k_init<<<(NN + 255) / 256, 256>>>();
    k_deg<<<(EE + 255) / 256, 256>>>(ei);
    k_scan<<<1, 1024>>>();
    k_scatter<<<(EE + 255) / 256, 256>>>(ei);
    k_fc1<<<(NN + 127) / 128, 256>>>(fd, fc1w, fc1b);
    k_gat<<<NN / 8, 256>>>(gatw, asrc, adst, gatb);
    k_gcn<<<NN / 8, 256>>>(gatw, asrc, adst, gcnw, gcnb, lng, lnb, out);
    k_logits<<<128, 256>>>(clfw);
    k_final<<<1, 32>>>(clfb, out);
}